// round 2
// baseline (speedup 1.0000x reference)
#include <cuda_runtime.h>

// LCA sparse coding, factorized: a@G = (a@phi^T)@phi - a, G = phi^T phi - I.
// All fp32; inner loops use packed fma.rn.f32x2 (2x FFMA throughput on sm_103a).

#define MB    32      // batch (GEMM M)
#define NPIX  3072    // pixels
#define NNEU  4096    // neurons
#define NSTEP 99      // NUM_STEPS - 1
#define KT    32      // k-tile
#define TN    32      // output tile width

__device__ float g_b[MB * NNEU];
__device__ float g_u[MB * NNEU];
__device__ float g_t[MB * NPIX];

// ---------------- packed f32x2 helpers ----------------
__device__ __forceinline__ void ffma2(unsigned long long& d,
                                      unsigned long long a,
                                      unsigned long long b) {
    asm("fma.rn.f32x2 %0, %1, %2, %0;" : "+l"(d) : "l"(a), "l"(b));
}
__device__ __forceinline__ unsigned long long pack2(float x, float y) {
    unsigned long long r;
    asm("mov.b64 %0, {%1, %2};" : "=l"(r) : "f"(x), "f"(y));
    return r;
}
__device__ __forceinline__ float2 unpack2(unsigned long long v) {
    float2 r;
    asm("mov.b64 {%0, %1}, %2;" : "=f"(r.x), "=f"(r.y) : "l"(v));
    return r;
}

// ---------------- tile loaders (128 threads) ----------------
// A tile: rows m=0..31, cols k0..k0+31 of A (row-major, stride lda).
// Stored transposed + duplicated: As2[k][m] = (a, a) packed.
__device__ __forceinline__ void load_A(const float* __restrict__ A, int lda, int k0,
                                       unsigned long long (*As2)[34], int tid) {
#pragma unroll
    for (int i = 0; i < 2; i++) {
        int f  = tid + i * 128;
        int m  = f >> 3;
        int kq = (f & 7) * 4;
        float4 v = *(const float4*)(A + m * lda + k0 + kq);
        As2[kq + 0][m] = pack2(v.x, v.x);
        As2[kq + 1][m] = pack2(v.y, v.y);
        As2[kq + 2][m] = pack2(v.z, v.z);
        As2[kq + 3][m] = pack2(v.w, v.w);
    }
}

// B tile, NN case: B[k0+row][n0+col] stored directly Bs[row][col].
__device__ __forceinline__ void load_B_nn(const float* __restrict__ B, int ldb,
                                          int k0, int n0, float (*Bs)[32], int tid) {
#pragma unroll
    for (int i = 0; i < 2; i++) {
        int f   = tid + i * 128;
        int row = f >> 3;
        int col = (f & 7) * 4;
        *(float4*)&Bs[row][col] = *(const float4*)(B + (size_t)(k0 + row) * ldb + n0 + col);
    }
}

// B tile, NT case (t = a@phi^T): output dim p, reduce dim k (= neuron n).
// Load phi[p0+prow][k0+kcol] and store transposed: BsT[k][p].
__device__ __forceinline__ void load_B_nt(const float* __restrict__ B, int ldb,
                                          int p0, int k0, float (*BsT)[36], int tid) {
#pragma unroll
    for (int i = 0; i < 2; i++) {
        int f    = tid + i * 128;
        int prow = f >> 3;
        int kcol = (f & 7) * 4;
        float4 v = *(const float4*)(B + (size_t)(p0 + prow) * ldb + k0 + kcol);
        BsT[kcol + 0][prow] = v.x;
        BsT[kcol + 1][prow] = v.y;
        BsT[kcol + 2][prow] = v.z;
        BsT[kcol + 3][prow] = v.w;
    }
}

// ---------------- inner micro-kernel ----------------
// Each thread: 2 m-rows x 4 n-cols. BROW = row stride (floats) of B smem tile.
template <int BROW>
__device__ __forceinline__ void mm_inner(const unsigned long long* As2,
                                         const float* Bs,
                                         int mg, int ng,
                                         unsigned long long acc[2][2]) {
#pragma unroll
    for (int k = 0; k < KT; k++) {
        ulonglong2 ap = *(const ulonglong2*)(As2 + k * 34 + 2 * mg);
        ulonglong2 bp = *(const ulonglong2*)(Bs + k * BROW + 4 * ng);
        ffma2(acc[0][0], ap.x, bp.x);
        ffma2(acc[0][1], ap.x, bp.y);
        ffma2(acc[1][0], ap.y, bp.x);
        ffma2(acc[1][1], ap.y, bp.y);
    }
}

// ---------------- init ----------------
__global__ void k_init(float* __restrict__ a_out) {
    int i = blockIdx.x * blockDim.x + threadIdx.x;
    if (i < MB * NNEU) {
        g_u[i]  = 0.0f;
        a_out[i] = 0.0f;
    }
}

// ---------------- b = x @ phi ----------------
__global__ void __launch_bounds__(128) k_gemm_b(const float* __restrict__ x,
                                                const float* __restrict__ phi) {
    __shared__ __align__(16) unsigned long long As2[KT][34];
    __shared__ __align__(16) float Bs[KT][32];
    int tid = threadIdx.x;
    int mg = tid >> 3, ng = tid & 7;
    int n0 = blockIdx.x * TN;
    unsigned long long acc[2][2] = {{0ull, 0ull}, {0ull, 0ull}};

    for (int k0 = 0; k0 < NPIX; k0 += KT) {
        load_A(x, NPIX, k0, As2, tid);
        load_B_nn(phi, NNEU, k0, n0, Bs, tid);
        __syncthreads();
        mm_inner<32>(&As2[0][0], &Bs[0][0], mg, ng, acc);
        __syncthreads();
    }
    int n = n0 + 4 * ng;
#pragma unroll
    for (int im = 0; im < 2; im++) {
        int m = 2 * mg + im;
        float2 c0 = unpack2(acc[im][0]);
        float2 c1 = unpack2(acc[im][1]);
        *(float4*)&g_b[m * NNEU + n] = make_float4(c0.x, c0.y, c1.x, c1.y);
    }
}

// ---------------- t = a @ phi^T  (t[m,p] = sum_n a[m,n]*phi[p,n]) ----------------
__global__ void __launch_bounds__(128) k_step_t(const float* __restrict__ a,
                                                const float* __restrict__ phi) {
    __shared__ __align__(16) unsigned long long As2[KT][34];
    __shared__ __align__(16) float BsT[KT][36];
    int tid = threadIdx.x;
    int mg = tid >> 3, ng = tid & 7;
    int p0 = blockIdx.x * TN;
    unsigned long long acc[2][2] = {{0ull, 0ull}, {0ull, 0ull}};

    for (int k0 = 0; k0 < NNEU; k0 += KT) {
        load_A(a, NNEU, k0, As2, tid);
        load_B_nt(phi, NNEU, p0, k0, BsT, tid);
        __syncthreads();
        mm_inner<36>(&As2[0][0], &BsT[0][0], mg, ng, acc);
        __syncthreads();
    }
    int p = p0 + 4 * ng;
#pragma unroll
    for (int im = 0; im < 2; im++) {
        int m = 2 * mg + im;
        float2 c0 = unpack2(acc[im][0]);
        float2 c1 = unpack2(acc[im][1]);
        *(float4*)&g_t[m * NPIX + p] = make_float4(c0.x, c0.y, c1.x, c1.y);
    }
}

// ---------------- c = t @ phi, fused LCA update ----------------
// du = b - (c - a) - u ; u += eta*du ; a = soft_threshold(u, lam)
__global__ void __launch_bounds__(128) k_step_update(const float* __restrict__ phi,
                                                     const float* __restrict__ lam_ptr,
                                                     float* __restrict__ a) {
    __shared__ __align__(16) unsigned long long As2[KT][34];
    __shared__ __align__(16) float Bs[KT][32];
    int tid = threadIdx.x;
    int mg = tid >> 3, ng = tid & 7;
    int n0 = blockIdx.x * TN;
    unsigned long long acc[2][2] = {{0ull, 0ull}, {0ull, 0ull}};

    for (int k0 = 0; k0 < NPIX; k0 += KT) {
        load_A(g_t, NPIX, k0, As2, tid);
        load_B_nn(phi, NNEU, k0, n0, Bs, tid);
        __syncthreads();
        mm_inner<32>(&As2[0][0], &Bs[0][0], mg, ng, acc);
        __syncthreads();
    }

    const float lam = *lam_ptr;
    const float ETA_F = (float)(0.001 / 0.03);
    int n = n0 + 4 * ng;
#pragma unroll
    for (int im = 0; im < 2; im++) {
        int m   = 2 * mg + im;
        int idx = m * NNEU + n;
        float2 c0 = unpack2(acc[im][0]);
        float2 c1 = unpack2(acc[im][1]);
        float c[4] = {c0.x, c0.y, c1.x, c1.y};
        float4 bb = *(const float4*)&g_b[idx];
        float4 uu = *(const float4*)&g_u[idx];
        float4 aa = *(const float4*)&a[idx];
        float bv[4] = {bb.x, bb.y, bb.z, bb.w};
        float uv[4] = {uu.x, uu.y, uu.z, uu.w};
        float av[4] = {aa.x, aa.y, aa.z, aa.w};
        float un[4], an[4];
#pragma unroll
        for (int j = 0; j < 4; j++) {
            float du = bv[j] - c[j] + av[j] - uv[j];
            un[j] = uv[j] + ETA_F * du;
            an[j] = (un[j] > lam) ? (un[j] - lam)
                  : ((un[j] < -lam) ? (un[j] + lam) : 0.0f);
        }
        *(float4*)&g_u[idx] = make_float4(un[0], un[1], un[2], un[3]);
        *(float4*)&a[idx]   = make_float4(an[0], an[1], an[2], an[3]);
    }
}

// ---------------- launch ----------------
extern "C" void kernel_launch(void* const* d_in, const int* in_sizes, int n_in,
                              void* d_out, int out_size) {
    const float* x   = (const float*)d_in[0];   // [32, 3072]
    const float* phi = (const float*)d_in[1];   // [3072, 4096]
    const float* lam = (const float*)d_in[2];   // scalar
    float* a = (float*)d_out;                   // [32, 4096]

    k_init<<<(MB * NNEU + 255) / 256, 256>>>(a);
    k_gemm_b<<<NNEU / TN, 128>>>(x, phi);

    for (int s = 0; s < NSTEP; s++) {
        k_step_t<<<NPIX / TN, 128>>>(a, phi);
        k_step_update<<<NNEU / TN, 128>>>(phi, lam, a);
    }
}

// round 3
// speedup vs baseline: 1.0015x; 1.0015x over previous
#include <cuda_runtime.h>

// LCA sparse coding, factorized: a@G = (a@phi^T)@phi - a, G = phi^T phi - I.
// All fp32; inner loops use packed fma.rn.f32x2 (2x FFMA throughput on sm_103a).

#define MB    32      // batch (GEMM M)
#define NPIX  3072    // pixels
#define NNEU  4096    // neurons
#define NSTEP 99      // NUM_STEPS - 1
#define KT    32      // k-tile
#define TN    32      // output tile width

__device__ float g_b[MB * NNEU];
__device__ float g_u[MB * NNEU];
__device__ float g_t[MB * NPIX];

// ---------------- packed f32x2 helpers ----------------
__device__ __forceinline__ void ffma2(unsigned long long& d,
                                      unsigned long long a,
                                      unsigned long long b) {
    asm("fma.rn.f32x2 %0, %1, %2, %0;" : "+l"(d) : "l"(a), "l"(b));
}
__device__ __forceinline__ unsigned long long pack2(float x, float y) {
    unsigned long long r;
    asm("mov.b64 %0, {%1, %2};" : "=l"(r) : "f"(x), "f"(y));
    return r;
}
__device__ __forceinline__ float2 unpack2(unsigned long long v) {
    float2 r;
    asm("mov.b64 {%0, %1}, %2;" : "=f"(r.x), "=f"(r.y) : "l"(v));
    return r;
}

// ---------------- tile loaders (128 threads) ----------------
// A tile: rows m=0..31, cols k0..k0+31 of A (row-major, stride lda).
// Stored transposed + duplicated: As2[k][m] = (a, a) packed.
__device__ __forceinline__ void load_A(const float* __restrict__ A, int lda, int k0,
                                       unsigned long long (*As2)[34], int tid) {
#pragma unroll
    for (int i = 0; i < 2; i++) {
        int f  = tid + i * 128;
        int m  = f >> 3;
        int kq = (f & 7) * 4;
        float4 v = *(const float4*)(A + m * lda + k0 + kq);
        As2[kq + 0][m] = pack2(v.x, v.x);
        As2[kq + 1][m] = pack2(v.y, v.y);
        As2[kq + 2][m] = pack2(v.z, v.z);
        As2[kq + 3][m] = pack2(v.w, v.w);
    }
}

// B tile, NN case: B[k0+row][n0+col] stored directly Bs[row][col].
__device__ __forceinline__ void load_B_nn(const float* __restrict__ B, int ldb,
                                          int k0, int n0, float (*Bs)[32], int tid) {
#pragma unroll
    for (int i = 0; i < 2; i++) {
        int f   = tid + i * 128;
        int row = f >> 3;
        int col = (f & 7) * 4;
        *(float4*)&Bs[row][col] = *(const float4*)(B + (size_t)(k0 + row) * ldb + n0 + col);
    }
}

// B tile, NT case (t = a@phi^T): output dim p, reduce dim k (= neuron n).
// Load phi[p0+prow][k0+kcol] and store transposed: BsT[k][p].
__device__ __forceinline__ void load_B_nt(const float* __restrict__ B, int ldb,
                                          int p0, int k0, float (*BsT)[36], int tid) {
#pragma unroll
    for (int i = 0; i < 2; i++) {
        int f    = tid + i * 128;
        int prow = f >> 3;
        int kcol = (f & 7) * 4;
        float4 v = *(const float4*)(B + (size_t)(p0 + prow) * ldb + k0 + kcol);
        BsT[kcol + 0][prow] = v.x;
        BsT[kcol + 1][prow] = v.y;
        BsT[kcol + 2][prow] = v.z;
        BsT[kcol + 3][prow] = v.w;
    }
}

// ---------------- inner micro-kernel ----------------
// Each thread: 2 m-rows x 4 n-cols. BROW = row stride (floats) of B smem tile.
template <int BROW>
__device__ __forceinline__ void mm_inner(const unsigned long long* As2,
                                         const float* Bs,
                                         int mg, int ng,
                                         unsigned long long acc[2][2]) {
#pragma unroll
    for (int k = 0; k < KT; k++) {
        ulonglong2 ap = *(const ulonglong2*)(As2 + k * 34 + 2 * mg);
        ulonglong2 bp = *(const ulonglong2*)(Bs + k * BROW + 4 * ng);
        ffma2(acc[0][0], ap.x, bp.x);
        ffma2(acc[0][1], ap.x, bp.y);
        ffma2(acc[1][0], ap.y, bp.x);
        ffma2(acc[1][1], ap.y, bp.y);
    }
}

// ---------------- init ----------------
__global__ void k_init(float* __restrict__ a_out) {
    int i = blockIdx.x * blockDim.x + threadIdx.x;
    if (i < MB * NNEU) {
        g_u[i]  = 0.0f;
        a_out[i] = 0.0f;
    }
}

// ---------------- b = x @ phi ----------------
__global__ void __launch_bounds__(128) k_gemm_b(const float* __restrict__ x,
                                                const float* __restrict__ phi) {
    __shared__ __align__(16) unsigned long long As2[KT][34];
    __shared__ __align__(16) float Bs[KT][32];
    int tid = threadIdx.x;
    int mg = tid >> 3, ng = tid & 7;
    int n0 = blockIdx.x * TN;
    unsigned long long acc[2][2] = {{0ull, 0ull}, {0ull, 0ull}};

    for (int k0 = 0; k0 < NPIX; k0 += KT) {
        load_A(x, NPIX, k0, As2, tid);
        load_B_nn(phi, NNEU, k0, n0, Bs, tid);
        __syncthreads();
        mm_inner<32>(&As2[0][0], &Bs[0][0], mg, ng, acc);
        __syncthreads();
    }
    int n = n0 + 4 * ng;
#pragma unroll
    for (int im = 0; im < 2; im++) {
        int m = 2 * mg + im;
        float2 c0 = unpack2(acc[im][0]);
        float2 c1 = unpack2(acc[im][1]);
        *(float4*)&g_b[m * NNEU + n] = make_float4(c0.x, c0.y, c1.x, c1.y);
    }
}

// ---------------- t = a @ phi^T  (t[m,p] = sum_n a[m,n]*phi[p,n]) ----------------
__global__ void __launch_bounds__(128) k_step_t(const float* __restrict__ a,
                                                const float* __restrict__ phi) {
    __shared__ __align__(16) unsigned long long As2[KT][34];
    __shared__ __align__(16) float BsT[KT][36];
    int tid = threadIdx.x;
    int mg = tid >> 3, ng = tid & 7;
    int p0 = blockIdx.x * TN;
    unsigned long long acc[2][2] = {{0ull, 0ull}, {0ull, 0ull}};

    for (int k0 = 0; k0 < NNEU; k0 += KT) {
        load_A(a, NNEU, k0, As2, tid);
        load_B_nt(phi, NNEU, p0, k0, BsT, tid);
        __syncthreads();
        mm_inner<36>(&As2[0][0], &BsT[0][0], mg, ng, acc);
        __syncthreads();
    }
    int p = p0 + 4 * ng;
#pragma unroll
    for (int im = 0; im < 2; im++) {
        int m = 2 * mg + im;
        float2 c0 = unpack2(acc[im][0]);
        float2 c1 = unpack2(acc[im][1]);
        *(float4*)&g_t[m * NPIX + p] = make_float4(c0.x, c0.y, c1.x, c1.y);
    }
}

// ---------------- c = t @ phi, fused LCA update ----------------
// du = b - (c - a) - u ; u += eta*du ; a = soft_threshold(u, lam)
__global__ void __launch_bounds__(128) k_step_update(const float* __restrict__ phi,
                                                     const float* __restrict__ lam_ptr,
                                                     float* __restrict__ a) {
    __shared__ __align__(16) unsigned long long As2[KT][34];
    __shared__ __align__(16) float Bs[KT][32];
    int tid = threadIdx.x;
    int mg = tid >> 3, ng = tid & 7;
    int n0 = blockIdx.x * TN;
    unsigned long long acc[2][2] = {{0ull, 0ull}, {0ull, 0ull}};

    for (int k0 = 0; k0 < NPIX; k0 += KT) {
        load_A(g_t, NPIX, k0, As2, tid);
        load_B_nn(phi, NNEU, k0, n0, Bs, tid);
        __syncthreads();
        mm_inner<32>(&As2[0][0], &Bs[0][0], mg, ng, acc);
        __syncthreads();
    }

    const float lam = *lam_ptr;
    const float ETA_F = (float)(0.001 / 0.03);
    int n = n0 + 4 * ng;
#pragma unroll
    for (int im = 0; im < 2; im++) {
        int m   = 2 * mg + im;
        int idx = m * NNEU + n;
        float2 c0 = unpack2(acc[im][0]);
        float2 c1 = unpack2(acc[im][1]);
        float c[4] = {c0.x, c0.y, c1.x, c1.y};
        float4 bb = *(const float4*)&g_b[idx];
        float4 uu = *(const float4*)&g_u[idx];
        float4 aa = *(const float4*)&a[idx];
        float bv[4] = {bb.x, bb.y, bb.z, bb.w};
        float uv[4] = {uu.x, uu.y, uu.z, uu.w};
        float av[4] = {aa.x, aa.y, aa.z, aa.w};
        float un[4], an[4];
#pragma unroll
        for (int j = 0; j < 4; j++) {
            float du = bv[j] - c[j] + av[j] - uv[j];
            un[j] = uv[j] + ETA_F * du;
            an[j] = (un[j] > lam) ? (un[j] - lam)
                  : ((un[j] < -lam) ? (un[j] + lam) : 0.0f);
        }
        *(float4*)&g_u[idx] = make_float4(un[0], un[1], un[2], un[3]);
        *(float4*)&a[idx]   = make_float4(an[0], an[1], an[2], an[3]);
    }
}

// ---------------- launch ----------------
extern "C" void kernel_launch(void* const* d_in, const int* in_sizes, int n_in,
                              void* d_out, int out_size) {
    const float* x   = (const float*)d_in[0];   // [32, 3072]
    const float* phi = (const float*)d_in[1];   // [3072, 4096]
    const float* lam = (const float*)d_in[2];   // scalar
    float* a = (float*)d_out;                   // [32, 4096]

    k_init<<<(MB * NNEU + 255) / 256, 256>>>(a);
    k_gemm_b<<<NNEU / TN, 128>>>(x, phi);

    for (int s = 0; s < NSTEP; s++) {
        k_step_t<<<NPIX / TN, 128>>>(a, phi);
        k_step_update<<<NNEU / TN, 128>>>(phi, lam, a);
    }
}